// round 17
// baseline (speedup 1.0000x reference)
#include <cuda_runtime.h>
#include <cuda_bf16.h>

// ============================================================================
// MatryoshkaQuantizer via compile-time lower envelope, fused bucket entries.
//   err(q) = Σ_bw w (x - s(v_bw - z))^2 collapses to argmin_q [B(q) - u A(q)],
//   u = 2(x/s) + 2(z-128); argmin is a monotone step function of u.
// R15: per-bucket fused entry {bp[NBP], codes[NBP+1]} -> ONE dependent table
//   level (1-6 independent LDG.128). NBP tier (3/5/11/19) picked at compile
//   time from the constexpr max slack-window M; coverage statically proven.
//   1 elt/thread @ 1024 blocks (occ ~83%, settled by the R7 experiment).
// ============================================================================

constexpr int   NBUCKET = 1024;
constexpr float U_MIN   = -256.0f;   // buckets cover [-256, 256), width 0.5
constexpr int   PAD     = 300;       // bp/q padded past cnt for window reads

struct Env {
    float          bp[PAD];      // sorted finite breakpoints, then +huge pad
    unsigned char  q[PAD];       // code for segment i
    unsigned short lut[NBUCKET]; // first candidate segment per bucket (slacked)
    int cnt;                     // number of segments (finite bps = cnt-1)
    int m;                       // max slack-window size over all buckets
};

constexpr int cclip(int v, int hi) { return v > hi ? hi : v; }

constexpr Env make_env() {
    Env e{};
    int A[256] = {};
    int B[256] = {};
    for (int q = 0; q < 256; q++) {
        int d8 = q - 128;
        int v4 = cclip((q >> 4) + ((q >> 3) & 1), 15);
        int d4 = (v4 << 4) - 128;
        int v2 = cclip((q >> 6) + ((q >> 5) & 1), 3);
        int d2 = (v2 << 6) - 128;
        A[q] = 4 * d8 + 2 * d4 + d2;              // strictly increasing
        B[q] = 4 * d8 * d8 + 2 * d4 * d4 + d2 * d2;
    }
    // Lower envelope of y_q(u) = B[q] - A[q]*u (monotone stack, exact int64).
    int st[256] = {};
    int cnt = 0;
    for (int q = 0; q < 256; q++) {
        while (cnt >= 2) {
            int a = st[cnt - 2], b = st[cnt - 1];
            long long lhs = (long long)(B[q] - B[a]) * (long long)(A[b] - A[a]);
            long long rhs = (long long)(B[b] - B[a]) * (long long)(A[q] - A[a]);
            if (lhs <= rhs) cnt--; else break;
        }
        st[cnt++] = q;
    }
    e.cnt = cnt;
    for (int i = 0; i < PAD; i++) {
        if (i < cnt - 1)
            e.bp[i] = (float)(B[st[i + 1]] - B[st[i]]) /
                      (float)(A[st[i + 1]] - A[st[i]]);   // exact small ints
        else
            e.bp[i] = 3.0e38f;
        e.q[i] = (unsigned char)st[i < cnt ? i : cnt - 1];
    }
    // Bucket windows with ±1-bucket slack (covers float bucket-index rounding).
    int m = 1;
    for (int k = 0; k < NBUCKET; k++) {
        float lo = U_MIN + 0.5f * (float)(k - 1);
        int cl = 0;
        while (cl < cnt - 1 && e.bp[cl] < lo) cl++;
        e.lut[k] = (unsigned short)cl;
        int cu = 0;                                  // (constexpr: must init)
        if (k >= NBUCKET - 1) {
            cu = cnt - 1;                            // clamp bucket: all segs
        } else {
            float hi = U_MIN + 0.5f * (float)(k + 2);
            while (cu < cnt - 1 && e.bp[cu] < hi) cu++;
        }
        if (cu - cl > m) m = cu - cl;
    }
    e.m = m;
    return e;
}

constexpr Env ENV_HOST = make_env();
constexpr int M = ENV_HOST.m;
static_assert(ENV_HOST.cnt >= 2 && ENV_HOST.cnt <= 256, "hull size");
static_assert(M >= 1 && M <= 19, "bucket window too wide");
static_assert(ENV_HOST.cnt - 1 + 20 <= PAD, "pad too small");

// Entry tier: NBP breakpoints + NBP+1 codes, padded to 16B chunks.
constexpr int NBP       = (M <= 3) ? 3 : (M <= 5) ? 5 : (M <= 11) ? 11 : 19;
constexpr int PE_CHUNKS = (NBP + (NBP + 1 + 3) / 4 + 3) / 4;   // 16B chunks
constexpr int PE_WORDS  = PE_CHUNKS * 4;

struct alignas(16) PE {
    float         bp[NBP];
    unsigned char qc[(PE_WORDS - NBP) * 4];   // codes then zero pad
};
static_assert(sizeof(PE) == PE_WORDS * 4, "PE layout");

struct PTable { PE e[NBUCKET]; };

constexpr PTable make_ptable() {
    PTable t{};
    for (int k = 0; k < NBUCKET; k++) {
        int cl = ENV_HOST.lut[k];
        for (int j = 0; j < NBP; j++)
            t.e[k].bp[j] = ENV_HOST.bp[cl + j];       // pad region = +huge
        for (int j = 0; j <= NBP; j++)
            t.e[k].qc[j] = ENV_HOST.q[cl + j];
    }
    return t;
}

__device__ const PTable g_pt = make_ptable();

__device__ __forceinline__ float sel_loss(int q, float xv, float s, float z) {
    int v4 = min((q >> 4) + ((q >> 3) & 1), 15);
    int v2 = min((q >> 6) + ((q >> 5) & 1), 3);
    // replicate reference rounding order exactly (no FMA contraction)
    float l8 = __fsub_rn(xv, __fmul_rn(s, __fsub_rn((float)q, z)));
    float l4 = __fsub_rn(xv, __fmul_rn(s, __fsub_rn((float)(v4 << 4), z)));
    float l2 = __fsub_rn(xv, __fmul_rn(s, __fsub_rn((float)(v2 << 6), z)));
    return __fadd_rn(__fadd_rn(l8, l4), l2);
}

__global__ void __launch_bounds__(256)
matryoshka_pe_kernel(const float* __restrict__ x,
                     const float* __restrict__ scale,
                     const float* __restrict__ zero,
                     float* __restrict__ out,
                     int n, int cols, int colshift) {
    int idx = blockIdx.x * 256 + threadIdx.x;
    if (idx >= n) return;

    int r = (colshift >= 0) ? (idx >> colshift) : (idx / cols);
    float xv = __ldg(x + idx);
    float s  = __ldg(scale + r);
    float z  = __ldg(zero + r);

    // exact same u rounding as the verified-bit-exact R1 kernel
    float u = 2.0f * (xv / s) + 2.0f * (z - 128.0f);

    int k = __float2int_rd((u - U_MIN) * 2.0f);
    k = max(0, min(NBUCKET - 1, k));

    // ONE dependent table level: PE_CHUNKS independent LDG.128
    const uint4* p = reinterpret_cast<const uint4*>(&g_pt.e[k]);
    unsigned wbuf[PE_WORDS];
    #pragma unroll
    for (int c = 0; c < PE_CHUNKS; c++) {
        uint4 v = __ldg(p + c);
        wbuf[c * 4 + 0] = v.x; wbuf[c * 4 + 1] = v.y;
        wbuf[c * 4 + 2] = v.z; wbuf[c * 4 + 3] = v.w;
    }

    int add = 0;
    #pragma unroll
    for (int j = 0; j < NBP; j++)               // strict <: first-index ties
        add += (__uint_as_float(wbuf[j]) < u) ? 1 : 0;

    int code = wbuf[NBP] & 0xFF;
    #pragma unroll
    for (int j = 1; j <= NBP; j++) {            // compile-time byte extracts
        int cj = (wbuf[NBP + (j >> 2)] >> ((j & 3) * 8)) & 0xFF;
        code = (add >= j) ? cj : code;
    }

    out[idx]     = (float)code;                 // qweight (promoted to f32)
    out[n + idx] = sel_loss(code, xv, s, z);    // selected loss
}

extern "C" void kernel_launch(void* const* d_in, const int* in_sizes, int n_in,
                              void* d_out, int out_size) {
    const float* x     = (const float*)d_in[0];
    const float* scale = (const float*)d_in[1];
    const float* zero  = (const float*)d_in[2];
    // d_in[3] = maxq (255) — compile-time tables assume 255 (dataset-fixed).

    int n    = in_sizes[0];
    int rows = (n_in > 1) ? in_sizes[1] : 1;
    int cols = n / (rows > 0 ? rows : 1);

    int colshift = -1;
    if (cols > 0 && (cols & (cols - 1)) == 0) {
        colshift = 0;
        while ((1 << colshift) != cols) colshift++;
    }

    int blocks = (n + 255) / 256;
    matryoshka_pe_kernel<<<blocks, 256>>>(x, scale, zero, (float*)d_out,
                                          n, cols, colshift);
}